// round 2
// baseline (speedup 1.0000x reference)
#include <cuda_runtime.h>
#include <math.h>

#define T_TOK 4096
#define H_DIM 1024
#define I_DIM 4096
#define NE 8
#define TOPK 2
#define ROWS_TOT (T_TOK * TOPK)

#define BM 64
#define BN 64
#define BK 16

// ---------------- scratch (static device globals; no runtime alloc) ----------------
__device__ int   g_cnt[NE];
__device__ int   g_off[NE];
__device__ int   g_tok[NE * T_TOK];            // token id per (expert, local row)
__device__ int   g_sel_e[T_TOK * TOPK];
__device__ int   g_sel_r[T_TOK * TOPK];
__device__ float g_sel_w[T_TOK * TOPK];
__device__ float g_act[ROWS_TOT * I_DIM];      // 128 MB: silu(g)*u per (row, I)
__device__ float g_down[ROWS_TOT * H_DIM];     // 32 MB: down-proj per row (unweighted)

// ---------------- reset ----------------
__global__ void reset_kernel() {
    if (threadIdx.x < NE) g_cnt[threadIdx.x] = 0;
}

// ---------------- router: logits, softmax, top-2, routing lists ----------------
__global__ void router_kernel(const float* __restrict__ x,
                              const float* __restrict__ rw,
                              float* __restrict__ out, int extras) {
    int t = blockIdx.x;
    int tid = threadIdx.x;           // 256 threads: warp e computes logit e
    int e = tid >> 5, lane = tid & 31;
    const float* xt = x + (size_t)t * H_DIM;
    float s = 0.f;
    for (int h = lane; h < H_DIM; h += 32) s += xt[h] * rw[h * NE + e];
    #pragma unroll
    for (int o = 16; o > 0; o >>= 1) s += __shfl_xor_sync(0xffffffffu, s, o);
    __shared__ float lg[NE];
    if (lane == 0) lg[e] = s;
    __syncthreads();
    if (tid == 0) {
        float mx = lg[0];
        #pragma unroll
        for (int i = 1; i < NE; i++) mx = fmaxf(mx, lg[i]);
        float p[NE]; float den = 0.f;
        #pragma unroll
        for (int i = 0; i < NE; i++) { p[i] = expf(lg[i] - mx); den += p[i]; }
        // top-2, ties -> lowest index (matches jax.lax.top_k)
        int e0 = 0;
        #pragma unroll
        for (int i = 1; i < NE; i++) if (p[i] > p[e0]) e0 = i;
        int e1 = (e0 == 0) ? 1 : 0;
        #pragma unroll
        for (int i = 0; i < NE; i++) if (i != e0 && p[i] > p[e1]) e1 = i;
        float p0 = p[e0], p1 = p[e1];
        float inv = 1.f / (p0 + p1);
        float w0 = p0 * inv, w1 = p1 * inv;
        int r0 = atomicAdd(&g_cnt[e0], 1);
        int r1 = atomicAdd(&g_cnt[e1], 1);
        g_tok[e0 * T_TOK + r0] = t;
        g_tok[e1 * T_TOK + r1] = t;
        g_sel_e[2 * t] = e0;     g_sel_r[2 * t] = r0;     g_sel_w[2 * t] = w0;
        g_sel_e[2 * t + 1] = e1; g_sel_r[2 * t + 1] = r1; g_sel_w[2 * t + 1] = w1;
        if (extras) {
            float* lo = out + (size_t)T_TOK * H_DIM;
            #pragma unroll
            for (int i = 0; i < NE; i++) lo[(size_t)t * NE + i] = lg[i];
            float* se = out + (size_t)T_TOK * H_DIM + (size_t)T_TOK * NE;
            se[2 * t] = (float)e0;
            se[2 * t + 1] = (float)e1;
        }
    }
}

// ---------------- exclusive scan of expert counts (E=8, trivial) ----------------
__global__ void scan_kernel() {
    int o = 0;
    for (int e = 0; e < NE; e++) { g_off[e] = o; o += g_cnt[e]; }
}

// ---------------- phase A: act = silu(X_e @ Wg_e) * (X_e @ Wu_e), gathered rows ----
__global__ __launch_bounds__(128, 4)
void gateup_kernel(const float* __restrict__ x,
                   const float* __restrict__ wg,
                   const float* __restrict__ wu) {
    int e = blockIdx.z;
    int cnt = g_cnt[e];
    int m0 = blockIdx.y * BM;
    if (m0 >= cnt) return;
    int n0 = blockIdx.x * BN;
    int off = g_off[e];

    __shared__ float sA[BK][BM];
    __shared__ float sBg[BK][BN];
    __shared__ float sBu[BK][BN];

    int tid = threadIdx.x;
    int tx = tid & 15;    // 16 cols of 4
    int ty = tid >> 4;    // 8 rows of 8

    float accg[8][4], accu[8][4];
    #pragma unroll
    for (int r = 0; r < 8; r++)
        #pragma unroll
        for (int c = 0; c < 4; c++) { accg[r][c] = 0.f; accu[r][c] = 0.f; }

    const float* wge = wg + (size_t)e * H_DIM * I_DIM;
    const float* wue = wu + (size_t)e * H_DIM * I_DIM;

    int am = tid >> 1;
    int ak = (tid & 1) * 8;
    const float* xrow = 0;
    { int mr = m0 + am; if (mr < cnt) xrow = x + (size_t)g_tok[e * T_TOK + mr] * H_DIM; }

    int bk = tid >> 3;        // 0..15
    int bn = (tid & 7) * 8;   // 0..56

    for (int k0 = 0; k0 < H_DIM; k0 += BK) {
        float av[8];
        if (xrow) {
            float4 a0 = *(const float4*)(xrow + k0 + ak);
            float4 a1 = *(const float4*)(xrow + k0 + ak + 4);
            av[0]=a0.x; av[1]=a0.y; av[2]=a0.z; av[3]=a0.w;
            av[4]=a1.x; av[5]=a1.y; av[6]=a1.z; av[7]=a1.w;
        } else {
            #pragma unroll
            for (int j = 0; j < 8; j++) av[j] = 0.f;
        }
        const float* bgp = wge + (size_t)(k0 + bk) * I_DIM + n0 + bn;
        const float* bup = wue + (size_t)(k0 + bk) * I_DIM + n0 + bn;
        float4 bg0 = *(const float4*)bgp;
        float4 bg1 = *(const float4*)(bgp + 4);
        float4 bu0 = *(const float4*)bup;
        float4 bu1 = *(const float4*)(bup + 4);

        #pragma unroll
        for (int j = 0; j < 8; j++) sA[ak + j][am] = av[j];
        *(float4*)&sBg[bk][bn]     = bg0;
        *(float4*)&sBg[bk][bn + 4] = bg1;
        *(float4*)&sBu[bk][bn]     = bu0;
        *(float4*)&sBu[bk][bn + 4] = bu1;
        __syncthreads();

        #pragma unroll
        for (int kk = 0; kk < BK; kk++) {
            float a[8];
            float4 t0 = *(const float4*)&sA[kk][ty * 8];
            float4 t1 = *(const float4*)&sA[kk][ty * 8 + 4];
            a[0]=t0.x; a[1]=t0.y; a[2]=t0.z; a[3]=t0.w;
            a[4]=t1.x; a[5]=t1.y; a[6]=t1.z; a[7]=t1.w;
            float4 bgv = *(const float4*)&sBg[kk][tx * 4];
            float4 buv = *(const float4*)&sBu[kk][tx * 4];
            float bga[4] = {bgv.x, bgv.y, bgv.z, bgv.w};
            float bua[4] = {buv.x, buv.y, buv.z, buv.w};
            #pragma unroll
            for (int r = 0; r < 8; r++)
                #pragma unroll
                for (int c = 0; c < 4; c++) {
                    accg[r][c] += a[r] * bga[c];
                    accu[r][c] += a[r] * bua[c];
                }
        }
        __syncthreads();
    }

    #pragma unroll
    for (int r = 0; r < 8; r++) {
        int gm = m0 + ty * 8 + r;
        if (gm < cnt) {
            float* dst = g_act + (size_t)(off + gm) * I_DIM + n0 + tx * 4;
            float4 o;
            float g0 = accg[r][0]; o.x = (g0 / (1.f + expf(-g0))) * accu[r][0];
            float g1 = accg[r][1]; o.y = (g1 / (1.f + expf(-g1))) * accu[r][1];
            float g2 = accg[r][2]; o.z = (g2 / (1.f + expf(-g2))) * accu[r][2];
            float g3 = accg[r][3]; o.w = (g3 / (1.f + expf(-g3))) * accu[r][3];
            *(float4*)dst = o;
        }
    }
}

// ---------------- phase B: down = act_e @ Wd_e ----------------
__global__ __launch_bounds__(128, 4)
void down_kernel(const float* __restrict__ wd) {
    int e = blockIdx.z;
    int cnt = g_cnt[e];
    int m0 = blockIdx.y * BM;
    if (m0 >= cnt) return;
    int n0 = blockIdx.x * BN;
    int off = g_off[e];

    __shared__ float sA[BK][BM];
    __shared__ float sB[BK][BN];

    int tid = threadIdx.x;
    int tx = tid & 15;
    int ty = tid >> 4;

    float acc[8][4];
    #pragma unroll
    for (int r = 0; r < 8; r++)
        #pragma unroll
        for (int c = 0; c < 4; c++) acc[r][c] = 0.f;

    const float* wde = wd + (size_t)e * I_DIM * H_DIM;

    int am = tid >> 1;
    int ak = (tid & 1) * 8;
    const float* arow = 0;
    { int mr = m0 + am; if (mr < cnt) arow = g_act + (size_t)(off + mr) * I_DIM; }

    int bk = tid >> 3;
    int bn = (tid & 7) * 8;

    for (int k0 = 0; k0 < I_DIM; k0 += BK) {
        float av[8];
        if (arow) {
            float4 a0 = *(const float4*)(arow + k0 + ak);
            float4 a1 = *(const float4*)(arow + k0 + ak + 4);
            av[0]=a0.x; av[1]=a0.y; av[2]=a0.z; av[3]=a0.w;
            av[4]=a1.x; av[5]=a1.y; av[6]=a1.z; av[7]=a1.w;
        } else {
            #pragma unroll
            for (int j = 0; j < 8; j++) av[j] = 0.f;
        }
        const float* bp = wde + (size_t)(k0 + bk) * H_DIM + n0 + bn;
        float4 b0 = *(const float4*)bp;
        float4 b1 = *(const float4*)(bp + 4);

        #pragma unroll
        for (int j = 0; j < 8; j++) sA[ak + j][am] = av[j];
        *(float4*)&sB[bk][bn]     = b0;
        *(float4*)&sB[bk][bn + 4] = b1;
        __syncthreads();

        #pragma unroll
        for (int kk = 0; kk < BK; kk++) {
            float a[8];
            float4 t0 = *(const float4*)&sA[kk][ty * 8];
            float4 t1 = *(const float4*)&sA[kk][ty * 8 + 4];
            a[0]=t0.x; a[1]=t0.y; a[2]=t0.z; a[3]=t0.w;
            a[4]=t1.x; a[5]=t1.y; a[6]=t1.z; a[7]=t1.w;
            float4 bv = *(const float4*)&sB[kk][tx * 4];
            float ba[4] = {bv.x, bv.y, bv.z, bv.w};
            #pragma unroll
            for (int r = 0; r < 8; r++)
                #pragma unroll
                for (int c = 0; c < 4; c++) acc[r][c] += a[r] * ba[c];
        }
        __syncthreads();
    }

    #pragma unroll
    for (int r = 0; r < 8; r++) {
        int gm = m0 + ty * 8 + r;
        if (gm < cnt) {
            float* dst = g_down + (size_t)(off + gm) * H_DIM + n0 + tx * 4;
            float4 o; o.x = acc[r][0]; o.y = acc[r][1]; o.z = acc[r][2]; o.w = acc[r][3];
            *(float4*)dst = o;
        }
    }
}

// ---------------- combine: out[t] = w0*down[slot0] + w1*down[slot1] (deterministic) ----
__global__ void combine_kernel(float* __restrict__ out) {
    int t = blockIdx.x;
    __shared__ int s0s, s1s;
    __shared__ float w0s, w1s;
    if (threadIdx.x == 0) {
        int e0 = g_sel_e[2 * t], e1 = g_sel_e[2 * t + 1];
        s0s = g_off[e0] + g_sel_r[2 * t];
        s1s = g_off[e1] + g_sel_r[2 * t + 1];
        w0s = g_sel_w[2 * t];
        w1s = g_sel_w[2 * t + 1];
    }
    __syncthreads();
    const float* d0 = g_down + (size_t)s0s * H_DIM;
    const float* d1 = g_down + (size_t)s1s * H_DIM;
    float* o = out + (size_t)t * H_DIM;
    float w0 = w0s, w1 = w1s;
    for (int h = threadIdx.x; h < H_DIM; h += blockDim.x)
        o[h] = w0 * d0[h] + w1 * d1[h];
}

// ---------------- launch ----------------
extern "C" void kernel_launch(void* const* d_in, const int* in_sizes, int n_in,
                              void* d_out, int out_size) {
    const float* x  = (const float*)d_in[0];   // hidden_states [4,1024,1024]
    const float* rw = (const float*)d_in[1];   // router_w [1024,8]
    const float* wg = (const float*)d_in[2];   // w_gate [8,1024,4096]
    const float* wu = (const float*)d_in[3];   // w_up   [8,1024,4096]
    const float* wd = (const float*)d_in[4];   // w_down [8,4096,1024]
    float* out = (float*)d_out;

    int extras = (out_size >= T_TOK * H_DIM + T_TOK * NE + T_TOK * TOPK) ? 1 : 0;

    reset_kernel<<<1, 32>>>();
    router_kernel<<<T_TOK, 256>>>(x, rw, out, extras);
    scan_kernel<<<1, 1>>>();

    dim3 ga(I_DIM / BN, T_TOK / BM, NE);   // (64, 64, 8); tiles past cnt[e] exit early
    gateup_kernel<<<ga, 128>>>(x, wg, wu);

    dim3 gb(H_DIM / BN, T_TOK / BM, NE);   // (16, 64, 8)
    down_kernel<<<gb, 128>>>(wd);

    combine_kernel<<<T_TOK, 256>>>(out);
}

// round 9
// speedup vs baseline: 1.0514x; 1.0514x over previous
#include <cuda_runtime.h>
#include <math.h>
#include <stdint.h>

#define T_TOK 4096
#define H_DIM 1024
#define I_DIM 4096
#define NE 8
#define TOPK 2
#define ROWS_TOT (T_TOK * TOPK)
#define ROWS_PAD (ROWS_TOT + 64)

#define BM 64
#define BN 64
#define BK 16

// ---------------- scratch (static device globals; ~162 MiB total, R2-proven level) ----
__device__ int   g_cnt[NE];
__device__ int   g_off[NE];
__device__ int   g_tok[NE * T_TOK];
__device__ int   g_sel_e[T_TOK * TOPK];
__device__ int   g_sel_r[T_TOK * TOPK];
__device__ float g_sel_w[T_TOK * TOPK];
__device__ float g_act[(size_t)ROWS_PAD * I_DIM];    // silu(g)*u
__device__ float g_down[(size_t)ROWS_PAD * H_DIM];   // down proj per row

// ---------------- packed f32x2 helpers (Blackwell FFMA2; the ONLY asm used) --------
#define FMA2(d, a, b) \
    asm("fma.rn.f32x2 %0, %1, %2, %0;" : "+l"(d) : "l"(a), "l"(b))
#define PACK2(d, f) \
    asm("mov.b64 %0, {%1, %1};" : "=l"(d) : "f"(f))
#define UNPACK2(lo, hi, d) \
    asm("mov.b64 {%0, %1}, %2;" : "=f"(lo), "=f"(hi) : "l"(d))

__device__ __forceinline__ float silu_mul(float g, float u) {
    return (g / (1.f + expf(-g))) * u;
}

// ---------------- reset / router / scan (byte-identical to R2, proven) ----------
__global__ void reset_kernel() { if (threadIdx.x < NE) g_cnt[threadIdx.x] = 0; }

__global__ void router_kernel(const float* __restrict__ x, const float* __restrict__ rw,
                              float* __restrict__ out, int extras) {
    int t = blockIdx.x, tid = threadIdx.x;
    int e = tid >> 5, lane = tid & 31;
    const float* xt = x + (size_t)t * H_DIM;
    float s = 0.f;
    for (int h = lane; h < H_DIM; h += 32) s += xt[h] * rw[h * NE + e];
    #pragma unroll
    for (int o = 16; o > 0; o >>= 1) s += __shfl_xor_sync(0xffffffffu, s, o);
    __shared__ float lg[NE];
    if (lane == 0) lg[e] = s;
    __syncthreads();
    if (tid == 0) {
        float mx = lg[0];
        #pragma unroll
        for (int i = 1; i < NE; i++) mx = fmaxf(mx, lg[i]);
        float p[NE];
        #pragma unroll
        for (int i = 0; i < NE; i++) p[i] = expf(lg[i] - mx);
        int e0 = 0;
        #pragma unroll
        for (int i = 1; i < NE; i++) if (p[i] > p[e0]) e0 = i;
        int e1 = (e0 == 0) ? 1 : 0;
        #pragma unroll
        for (int i = 0; i < NE; i++) if (i != e0 && p[i] > p[e1]) e1 = i;
        float p0 = p[e0], p1 = p[e1];
        float inv = 1.f / (p0 + p1);
        int r0 = atomicAdd(&g_cnt[e0], 1);
        int r1 = atomicAdd(&g_cnt[e1], 1);
        g_tok[e0 * T_TOK + r0] = t;
        g_tok[e1 * T_TOK + r1] = t;
        g_sel_e[2 * t] = e0;     g_sel_r[2 * t] = r0;     g_sel_w[2 * t] = p0 * inv;
        g_sel_e[2 * t + 1] = e1; g_sel_r[2 * t + 1] = r1; g_sel_w[2 * t + 1] = p1 * inv;
        if (extras) {
            float* lo = out + (size_t)T_TOK * H_DIM;
            #pragma unroll
            for (int i = 0; i < NE; i++) lo[(size_t)t * NE + i] = lg[i];
            float* se = out + (size_t)T_TOK * H_DIM + (size_t)T_TOK * NE;
            se[2 * t] = (float)e0;
            se[2 * t + 1] = (float)e1;
        }
    }
}

__global__ void scan_kernel() {
    int o = 0;
    for (int e = 0; e < NE; e++) { g_off[e] = o; o += g_cnt[e]; }
}

// ==================================================================================
// Phase A (R2 skeleton + FFMA2): act = silu(X Wg) * (X Wu), gathered rows.
// Thread tile 8m x 4n per matrix; m packed in f32x2 pairs (adjacent in sA rows ->
// ulonglong2 LDS loads A pairs directly), B replicated (b,b) via one mov.b64 each.
// Accumulators: 16 u64 per matrix (named scalar-style vector components only).
// ==================================================================================
__global__ __launch_bounds__(128, 4)
void gateup_kernel(const float* __restrict__ x,
                   const float* __restrict__ wg,
                   const float* __restrict__ wu) {
    int e = blockIdx.z;
    int cnt = g_cnt[e];
    int m0 = blockIdx.y * BM;
    if (m0 >= cnt) return;
    int n0 = blockIdx.x * BN;
    int off = g_off[e];

    __shared__ __align__(16) float sA[BK][BM];
    __shared__ __align__(16) float sBg[BK][BN];
    __shared__ __align__(16) float sBu[BK][BN];

    int tid = threadIdx.x;
    int tx = tid & 15;    // 16 n-cols of 4
    int ty = tid >> 4;    // 8 m-rows of 8

    // acc pairs: gPN / uPN, P = m-pair 0..3 (rows 2P,2P+1), N = col 0..3
    unsigned long long g00=0,g01=0,g02=0,g03=0, g10=0,g11=0,g12=0,g13=0;
    unsigned long long g20=0,g21=0,g22=0,g23=0, g30=0,g31=0,g32=0,g33=0;
    unsigned long long u00=0,u01=0,u02=0,u03=0, u10=0,u11=0,u12=0,u13=0;
    unsigned long long u20=0,u21=0,u22=0,u23=0, u30=0,u31=0,u32=0,u33=0;

    const float* wge = wg + (size_t)e * H_DIM * I_DIM;
    const float* wue = wu + (size_t)e * H_DIM * I_DIM;

    int am = tid >> 1;
    int ak = (tid & 1) * 8;
    const float* xrow = 0;
    { int mr = m0 + am; if (mr < cnt) xrow = x + (size_t)g_tok[e * T_TOK + mr] * H_DIM; }

    int bk = tid >> 3;        // 0..15
    int bn = (tid & 7) * 8;   // 0..56

    for (int k0 = 0; k0 < H_DIM; k0 += BK) {
        float av[8];
        if (xrow) {
            float4 a0 = *(const float4*)(xrow + k0 + ak);
            float4 a1 = *(const float4*)(xrow + k0 + ak + 4);
            av[0]=a0.x; av[1]=a0.y; av[2]=a0.z; av[3]=a0.w;
            av[4]=a1.x; av[5]=a1.y; av[6]=a1.z; av[7]=a1.w;
        } else {
            #pragma unroll
            for (int j = 0; j < 8; j++) av[j] = 0.f;
        }
        const float* bgp = wge + (size_t)(k0 + bk) * I_DIM + n0 + bn;
        const float* bup = wue + (size_t)(k0 + bk) * I_DIM + n0 + bn;
        float4 bg0 = *(const float4*)bgp;
        float4 bg1 = *(const float4*)(bgp + 4);
        float4 bu0 = *(const float4*)bup;
        float4 bu1 = *(const float4*)(bup + 4);

        #pragma unroll
        for (int j = 0; j < 8; j++) sA[ak + j][am] = av[j];
        *(float4*)&sBg[bk][bn]     = bg0;
        *(float4*)&sBg[bk][bn + 4] = bg1;
        *(float4*)&sBu[bk][bn]     = bu0;
        *(float4*)&sBu[bk][bn + 4] = bu1;
        __syncthreads();

        #pragma unroll
        for (int kk = 0; kk < BK; kk++) {
            // A: 4 m-pairs, packed directly by 128-bit shared loads
            ulonglong2 av0 = *(const ulonglong2*)&sA[kk][ty * 8];      // pairs (m0m1),(m2m3)
            ulonglong2 av1 = *(const ulonglong2*)&sA[kk][ty * 8 + 4];  // pairs (m4m5),(m6m7)
            float4 bgv = *(const float4*)&sBg[kk][tx * 4];
            float4 buv = *(const float4*)&sBu[kk][tx * 4];
            unsigned long long pg0, pg1, pg2, pg3, pu0, pu1, pu2, pu3;
            PACK2(pg0, bgv.x); PACK2(pg1, bgv.y); PACK2(pg2, bgv.z); PACK2(pg3, bgv.w);
            PACK2(pu0, buv.x); PACK2(pu1, buv.y); PACK2(pu2, buv.z); PACK2(pu3, buv.w);

            FMA2(g00, av0.x, pg0); FMA2(g01, av0.x, pg1); FMA2(g02, av0.x, pg2); FMA2(g03, av0.x, pg3);
            FMA2(g10, av0.y, pg0); FMA2(g11, av0.y, pg1); FMA2(g12, av0.y, pg2); FMA2(g13, av0.y, pg3);
            FMA2(g20, av1.x, pg0); FMA2(g21, av1.x, pg1); FMA2(g22, av1.x, pg2); FMA2(g23, av1.x, pg3);
            FMA2(g30, av1.y, pg0); FMA2(g31, av1.y, pg1); FMA2(g32, av1.y, pg2); FMA2(g33, av1.y, pg3);

            FMA2(u00, av0.x, pu0); FMA2(u01, av0.x, pu1); FMA2(u02, av0.x, pu2); FMA2(u03, av0.x, pu3);
            FMA2(u10, av0.y, pu0); FMA2(u11, av0.y, pu1); FMA2(u12, av0.y, pu2); FMA2(u13, av0.y, pu3);
            FMA2(u20, av1.x, pu0); FMA2(u21, av1.x, pu1); FMA2(u22, av1.x, pu2); FMA2(u23, av1.x, pu3);
            FMA2(u30, av1.y, pu0); FMA2(u31, av1.y, pu1); FMA2(u32, av1.y, pu2); FMA2(u33, av1.y, pu3);
        }
        __syncthreads();
    }

    // epilogue: unpack m-pairs, silu(g)*u, store float4 per row (same guards as R2)
#define EPI_GU(P, GA, GB, GC, GD, UA, UB, UC, UD)                                \
    do {                                                                         \
        float gl0, gh0, gl1, gh1, gl2, gh2, gl3, gh3;                            \
        float ql0, qh0, ql1, qh1, ql2, qh2, ql3, qh3;                            \
        UNPACK2(gl0, gh0, GA); UNPACK2(gl1, gh1, GB);                            \
        UNPACK2(gl2, gh2, GC); UNPACK2(gl3, gh3, GD);                            \
        UNPACK2(ql0, qh0, UA); UNPACK2(ql1, qh1, UB);                            \
        UNPACK2(ql2, qh2, UC); UNPACK2(ql3, qh3, UD);                            \
        int gmL = m0 + ty * 8 + 2 * (P);                                         \
        if (gmL < cnt) {                                                         \
            float4 o;                                                            \
            o.x = silu_mul(gl0, ql0); o.y = silu_mul(gl1, ql1);                  \
            o.z = silu_mul(gl2, ql2); o.w = silu_mul(gl3, ql3);                  \
            *(float4*)(g_act + (size_t)(off + gmL) * I_DIM + n0 + tx * 4) = o;   \
        }                                                                        \
        if (gmL + 1 < cnt) {                                                     \
            float4 o;                                                            \
            o.x = silu_mul(gh0, qh0); o.y = silu_mul(gh1, qh1);                  \
            o.z = silu_mul(gh2, qh2); o.w = silu_mul(gh3, qh3);                  \
            *(float4*)(g_act + (size_t)(off + gmL + 1) * I_DIM + n0 + tx * 4) = o; \
        }                                                                        \
    } while (0)

    EPI_GU(0, g00, g01, g02, g03, u00, u01, u02, u03);
    EPI_GU(1, g10, g11, g12, g13, u10, u11, u12, u13);
    EPI_GU(2, g20, g21, g22, g23, u20, u21, u22, u23);
    EPI_GU(3, g30, g31, g32, g33, u30, u31, u32, u33);
#undef EPI_GU
}

// ---------------- phase B (R2 skeleton + FFMA2): down = act_e @ Wd_e ----------------
__global__ __launch_bounds__(128, 4)
void down_kernel(const float* __restrict__ wd) {
    int e = blockIdx.z;
    int cnt = g_cnt[e];
    int m0 = blockIdx.y * BM;
    if (m0 >= cnt) return;
    int n0 = blockIdx.x * BN;
    int off = g_off[e];

    __shared__ __align__(16) float sA[BK][BM];
    __shared__ __align__(16) float sB[BK][BN];

    int tid = threadIdx.x;
    int tx = tid & 15;
    int ty = tid >> 4;

    unsigned long long d00=0,d01=0,d02=0,d03=0, d10=0,d11=0,d12=0,d13=0;
    unsigned long long d20=0,d21=0,d22=0,d23=0, d30=0,d31=0,d32=0,d33=0;

    const float* wde = wd + (size_t)e * I_DIM * H_DIM;

    int am = tid >> 1;
    int ak = (tid & 1) * 8;
    const float* arow = 0;
    { int mr = m0 + am; if (mr < cnt) arow = g_act + (size_t)(off + mr) * I_DIM; }

    int bk = tid >> 3;
    int bn = (tid & 7) * 8;

    for (int k0 = 0; k0 < I_DIM; k0 += BK) {
        float av[8];
        if (arow) {
            float4 a0 = *(const float4*)(arow + k0 + ak);
            float4 a1 = *(const float4*)(arow + k0 + ak + 4);
            av[0]=a0.x; av[1]=a0.y; av[2]=a0.z; av[3]=a0.w;
            av[4]=a1.x; av[5]=a1.y; av[6]=a1.z; av[7]=a1.w;
        } else {
            #pragma unroll
            for (int j = 0; j < 8; j++) av[j] = 0.f;
        }
        const float* bp = wde + (size_t)(k0 + bk) * H_DIM + n0 + bn;
        float4 b0 = *(const float4*)bp;
        float4 b1 = *(const float4*)(bp + 4);

        #pragma unroll
        for (int j = 0; j < 8; j++) sA[ak + j][am] = av[j];
        *(float4*)&sB[bk][bn]     = b0;
        *(float4*)&sB[bk][bn + 4] = b1;
        __syncthreads();

        #pragma unroll
        for (int kk = 0; kk < BK; kk++) {
            ulonglong2 av0 = *(const ulonglong2*)&sA[kk][ty * 8];
            ulonglong2 av1 = *(const ulonglong2*)&sA[kk][ty * 8 + 4];
            float4 bv = *(const float4*)&sB[kk][tx * 4];
            unsigned long long pb0, pb1, pb2, pb3;
            PACK2(pb0, bv.x); PACK2(pb1, bv.y); PACK2(pb2, bv.z); PACK2(pb3, bv.w);

            FMA2(d00, av0.x, pb0); FMA2(d01, av0.x, pb1); FMA2(d02, av0.x, pb2); FMA2(d03, av0.x, pb3);
            FMA2(d10, av0.y, pb0); FMA2(d11, av0.y, pb1); FMA2(d12, av0.y, pb2); FMA2(d13, av0.y, pb3);
            FMA2(d20, av1.x, pb0); FMA2(d21, av1.x, pb1); FMA2(d22, av1.x, pb2); FMA2(d23, av1.x, pb3);
            FMA2(d30, av1.y, pb0); FMA2(d31, av1.y, pb1); FMA2(d32, av1.y, pb2); FMA2(d33, av1.y, pb3);
        }
        __syncthreads();
    }

#define EPI_DN(P, DA, DB, DC, DD)                                                \
    do {                                                                         \
        float l0, h0, l1, h1, l2, h2, l3, h3;                                    \
        UNPACK2(l0, h0, DA); UNPACK2(l1, h1, DB);                                \
        UNPACK2(l2, h2, DC); UNPACK2(l3, h3, DD);                                \
        int gmL = m0 + ty * 8 + 2 * (P);                                         \
        if (gmL < cnt) {                                                         \
            float4 o; o.x = l0; o.y = l1; o.z = l2; o.w = l3;                    \
            *(float4*)(g_down + (size_t)(off + gmL) * H_DIM + n0 + tx * 4) = o;  \
        }                                                                        \
        if (gmL + 1 < cnt) {                                                     \
            float4 o; o.x = h0; o.y = h1; o.z = h2; o.w = h3;                    \
            *(float4*)(g_down + (size_t)(off + gmL + 1) * H_DIM + n0 + tx * 4) = o; \
        }                                                                        \
    } while (0)

    EPI_DN(0, d00, d01, d02, d03);
    EPI_DN(1, d10, d11, d12, d13);
    EPI_DN(2, d20, d21, d22, d23);
    EPI_DN(3, d30, d31, d32, d33);
#undef EPI_DN
}

// ---------------- combine (proven) ----------------
__global__ void combine_kernel(float* __restrict__ out) {
    int t = blockIdx.x;
    __shared__ int s0s, s1s;
    __shared__ float w0s, w1s;
    if (threadIdx.x == 0) {
        int e0 = g_sel_e[2 * t], e1 = g_sel_e[2 * t + 1];
        s0s = g_off[e0] + g_sel_r[2 * t];
        s1s = g_off[e1] + g_sel_r[2 * t + 1];
        w0s = g_sel_w[2 * t];
        w1s = g_sel_w[2 * t + 1];
    }
    __syncthreads();
    const float* d0 = g_down + (size_t)s0s * H_DIM;
    const float* d1 = g_down + (size_t)s1s * H_DIM;
    float* o = out + (size_t)t * H_DIM;
    float w0 = w0s, w1 = w1s;
    for (int h = threadIdx.x; h < H_DIM; h += blockDim.x)
        o[h] = w0 * d0[h] + w1 * d1[h];
}

// ---------------- launch (identical shape to proven R2) ----------------
extern "C" void kernel_launch(void* const* d_in, const int* in_sizes, int n_in,
                              void* d_out, int out_size) {
    const float* x  = (const float*)d_in[0];
    const float* rw = (const float*)d_in[1];
    const float* wg = (const float*)d_in[2];
    const float* wu = (const float*)d_in[3];
    const float* wd = (const float*)d_in[4];
    float* out = (float*)d_out;

    int extras = (out_size >= T_TOK * H_DIM + T_TOK * NE + T_TOK * TOPK) ? 1 : 0;

    reset_kernel<<<1, 32>>>();
    router_kernel<<<T_TOK, 256>>>(x, rw, out, extras);
    scan_kernel<<<1, 1>>>();

    dim3 ga(I_DIM / BN, T_TOK / BM, NE);   // (64, 64, 8)
    gateup_kernel<<<ga, 128>>>(x, wg, wu);

    dim3 gb(H_DIM / BN, T_TOK / BM, NE);   // (16, 64, 8)
    down_kernel<<<gb, 128>>>(wd);

    combine_kernel<<<T_TOK, 256>>>(out);
}

// round 10
// speedup vs baseline: 1.0559x; 1.0043x over previous
#include <cuda_runtime.h>
#include <math.h>
#include <stdint.h>

#define T_TOK 4096
#define H_DIM 1024
#define I_DIM 4096
#define NE 8
#define TOPK 2
#define ROWS_TOT (T_TOK * TOPK)
#define ROWS_PAD (ROWS_TOT + 64)

#define BM 64
#define BN 64
#define BK 16

// ---------------- scratch (static device globals; ~162 MiB, R2/R9-proven level) ----
__device__ int   g_cnt[NE];
__device__ int   g_off[NE];
__device__ int   g_tok[NE * T_TOK];
__device__ int   g_sel_e[T_TOK * TOPK];
__device__ int   g_sel_r[T_TOK * TOPK];
__device__ float g_sel_w[T_TOK * TOPK];
__device__ float g_act[(size_t)ROWS_PAD * I_DIM];    // silu(g)*u
__device__ float g_down[(size_t)ROWS_PAD * H_DIM];   // down proj per row

// ---------------- packed f32x2 helpers (proven guard-safe in R9) -------------------
#define FMA2(d, a, b) \
    asm("fma.rn.f32x2 %0, %1, %2, %0;" : "+l"(d) : "l"(a), "l"(b))
#define PACK2(d, f) \
    asm("mov.b64 %0, {%1, %1};" : "=l"(d) : "f"(f))
#define UNPACK2(lo, hi, d) \
    asm("mov.b64 {%0, %1}, %2;" : "=f"(lo), "=f"(hi) : "l"(d))

__device__ __forceinline__ float silu_mul(float g, float u) {
    return (g / (1.f + expf(-g))) * u;
}

// ---------------- reset / router / scan (proven) ----------------
__global__ void reset_kernel() { if (threadIdx.x < NE) g_cnt[threadIdx.x] = 0; }

__global__ void router_kernel(const float* __restrict__ x, const float* __restrict__ rw,
                              float* __restrict__ out, int extras) {
    int t = blockIdx.x, tid = threadIdx.x;
    int e = tid >> 5, lane = tid & 31;
    const float* xt = x + (size_t)t * H_DIM;
    float s = 0.f;
    for (int h = lane; h < H_DIM; h += 32) s += xt[h] * rw[h * NE + e];
    #pragma unroll
    for (int o = 16; o > 0; o >>= 1) s += __shfl_xor_sync(0xffffffffu, s, o);
    __shared__ float lg[NE];
    if (lane == 0) lg[e] = s;
    __syncthreads();
    if (tid == 0) {
        float mx = lg[0];
        #pragma unroll
        for (int i = 1; i < NE; i++) mx = fmaxf(mx, lg[i]);
        float p[NE];
        #pragma unroll
        for (int i = 0; i < NE; i++) p[i] = expf(lg[i] - mx);
        int e0 = 0;
        #pragma unroll
        for (int i = 1; i < NE; i++) if (p[i] > p[e0]) e0 = i;
        int e1 = (e0 == 0) ? 1 : 0;
        #pragma unroll
        for (int i = 0; i < NE; i++) if (i != e0 && p[i] > p[e1]) e1 = i;
        float p0 = p[e0], p1 = p[e1];
        float inv = 1.f / (p0 + p1);
        int r0 = atomicAdd(&g_cnt[e0], 1);
        int r1 = atomicAdd(&g_cnt[e1], 1);
        g_tok[e0 * T_TOK + r0] = t;
        g_tok[e1 * T_TOK + r1] = t;
        g_sel_e[2 * t] = e0;     g_sel_r[2 * t] = r0;     g_sel_w[2 * t] = p0 * inv;
        g_sel_e[2 * t + 1] = e1; g_sel_r[2 * t + 1] = r1; g_sel_w[2 * t + 1] = p1 * inv;
        if (extras) {
            float* lo = out + (size_t)T_TOK * H_DIM;
            #pragma unroll
            for (int i = 0; i < NE; i++) lo[(size_t)t * NE + i] = lg[i];
            float* se = out + (size_t)T_TOK * H_DIM + (size_t)T_TOK * NE;
            se[2 * t] = (float)e0;
            se[2 * t + 1] = (float)e1;
        }
    }
}

__global__ void scan_kernel() {
    int o = 0;
    for (int e = 0; e < NE; e++) { g_off[e] = o; o += g_cnt[e]; }
}

// ==================================================================================
// R9 math + software pipeline: register prefetch of chunk i+1 globals under chunk i
// compute, double-buffered smem (ONE barrier per chunk). FFMA2 kept for issue-slot
// headroom (fp32 ALU width is the roofline; target is stall elimination).
// __launch_bounds__(128,3): reg cap 168 >> ~143 needed -> no spill possible.
// ==================================================================================
__global__ __launch_bounds__(128, 3)
void gateup_kernel(const float* __restrict__ x,
                   const float* __restrict__ wg,
                   const float* __restrict__ wu) {
    int e = blockIdx.z;
    int cnt = g_cnt[e];
    int m0 = blockIdx.y * BM;
    if (m0 >= cnt) return;
    int n0 = blockIdx.x * BN;
    int off = g_off[e];

    __shared__ __align__(16) float sA[2][BK][BM];
    __shared__ __align__(16) float sBg[2][BK][BN];
    __shared__ __align__(16) float sBu[2][BK][BN];

    int tid = threadIdx.x;
    int tx = tid & 15;
    int ty = tid >> 4;

    unsigned long long g00=0,g01=0,g02=0,g03=0, g10=0,g11=0,g12=0,g13=0;
    unsigned long long g20=0,g21=0,g22=0,g23=0, g30=0,g31=0,g32=0,g33=0;
    unsigned long long u00=0,u01=0,u02=0,u03=0, u10=0,u11=0,u12=0,u13=0;
    unsigned long long u20=0,u21=0,u22=0,u23=0, u30=0,u31=0,u32=0,u33=0;

    const float* wge = wg + (size_t)e * H_DIM * I_DIM;
    const float* wue = wu + (size_t)e * H_DIM * I_DIM;

    int am = tid >> 1;
    int ak = (tid & 1) * 8;
    const float* xrow = 0;
    { int mr = m0 + am; if (mr < cnt) xrow = x + (size_t)g_tok[e * T_TOK + mr] * H_DIM; }

    int bk = tid >> 3;
    int bn = (tid & 7) * 8;

    float4 pa0, pa1, pbg0, pbg1, pbu0, pbu1;

#define LOADCH(k0_) do {                                                         \
    if (xrow) {                                                                  \
        pa0 = *(const float4*)(xrow + (k0_) + ak);                               \
        pa1 = *(const float4*)(xrow + (k0_) + ak + 4);                           \
    } else {                                                                     \
        pa0.x = pa0.y = pa0.z = pa0.w = 0.f;                                     \
        pa1 = pa0;                                                               \
    }                                                                            \
    const float* bgp_ = wge + (size_t)((k0_) + bk) * I_DIM + n0 + bn;            \
    const float* bup_ = wue + (size_t)((k0_) + bk) * I_DIM + n0 + bn;            \
    pbg0 = *(const float4*)bgp_;  pbg1 = *(const float4*)(bgp_ + 4);             \
    pbu0 = *(const float4*)bup_;  pbu1 = *(const float4*)(bup_ + 4);             \
} while (0)

    LOADCH(0);

    int buf = 0;
    for (int k0 = 0; k0 < H_DIM; k0 += BK, buf ^= 1) {
        // stage prefetched chunk into buf (previous compute on buf finished:
        // every warp passed the prior barrier before its STS here)
        sA[buf][ak + 0][am] = pa0.x;
        sA[buf][ak + 1][am] = pa0.y;
        sA[buf][ak + 2][am] = pa0.z;
        sA[buf][ak + 3][am] = pa0.w;
        sA[buf][ak + 4][am] = pa1.x;
        sA[buf][ak + 5][am] = pa1.y;
        sA[buf][ak + 6][am] = pa1.z;
        sA[buf][ak + 7][am] = pa1.w;
        *(float4*)&sBg[buf][bk][bn]     = pbg0;
        *(float4*)&sBg[buf][bk][bn + 4] = pbg1;
        *(float4*)&sBu[buf][bk][bn]     = pbu0;
        *(float4*)&sBu[buf][bk][bn + 4] = pbu1;
        __syncthreads();

        if (k0 + BK < H_DIM) LOADCH(k0 + BK);   // latency hidden under compute

        #pragma unroll
        for (int kk = 0; kk < BK; kk++) {
            ulonglong2 av0 = *(const ulonglong2*)&sA[buf][kk][ty * 8];
            ulonglong2 av1 = *(const ulonglong2*)&sA[buf][kk][ty * 8 + 4];
            float4 bgv = *(const float4*)&sBg[buf][kk][tx * 4];
            float4 buv = *(const float4*)&sBu[buf][kk][tx * 4];
            unsigned long long pg0, pg1, pg2, pg3, pu0, pu1, pu2, pu3;
            PACK2(pg0, bgv.x); PACK2(pg1, bgv.y); PACK2(pg2, bgv.z); PACK2(pg3, bgv.w);
            PACK2(pu0, buv.x); PACK2(pu1, buv.y); PACK2(pu2, buv.z); PACK2(pu3, buv.w);

            FMA2(g00, av0.x, pg0); FMA2(g01, av0.x, pg1); FMA2(g02, av0.x, pg2); FMA2(g03, av0.x, pg3);
            FMA2(g10, av0.y, pg0); FMA2(g11, av0.y, pg1); FMA2(g12, av0.y, pg2); FMA2(g13, av0.y, pg3);
            FMA2(g20, av1.x, pg0); FMA2(g21, av1.x, pg1); FMA2(g22, av1.x, pg2); FMA2(g23, av1.x, pg3);
            FMA2(g30, av1.y, pg0); FMA2(g31, av1.y, pg1); FMA2(g32, av1.y, pg2); FMA2(g33, av1.y, pg3);

            FMA2(u00, av0.x, pu0); FMA2(u01, av0.x, pu1); FMA2(u02, av0.x, pu2); FMA2(u03, av0.x, pu3);
            FMA2(u10, av0.y, pu0); FMA2(u11, av0.y, pu1); FMA2(u12, av0.y, pu2); FMA2(u13, av0.y, pu3);
            FMA2(u20, av1.x, pu0); FMA2(u21, av1.x, pu1); FMA2(u22, av1.x, pu2); FMA2(u23, av1.x, pu3);
            FMA2(u30, av1.y, pu0); FMA2(u31, av1.y, pu1); FMA2(u32, av1.y, pu2); FMA2(u33, av1.y, pu3);
        }
    }
#undef LOADCH

#define EPI_GU(P, GA, GB, GC, GD, UA, UB, UC, UD)                                \
    do {                                                                         \
        float gl0, gh0, gl1, gh1, gl2, gh2, gl3, gh3;                            \
        float ql0, qh0, ql1, qh1, ql2, qh2, ql3, qh3;                            \
        UNPACK2(gl0, gh0, GA); UNPACK2(gl1, gh1, GB);                            \
        UNPACK2(gl2, gh2, GC); UNPACK2(gl3, gh3, GD);                            \
        UNPACK2(ql0, qh0, UA); UNPACK2(ql1, qh1, UB);                            \
        UNPACK2(ql2, qh2, UC); UNPACK2(ql3, qh3, UD);                            \
        int gmL = m0 + ty * 8 + 2 * (P);                                         \
        if (gmL < cnt) {                                                         \
            float4 o;                                                            \
            o.x = silu_mul(gl0, ql0); o.y = silu_mul(gl1, ql1);                  \
            o.z = silu_mul(gl2, ql2); o.w = silu_mul(gl3, ql3);                  \
            *(float4*)(g_act + (size_t)(off + gmL) * I_DIM + n0 + tx * 4) = o;   \
        }                                                                        \
        if (gmL + 1 < cnt) {                                                     \
            float4 o;                                                            \
            o.x = silu_mul(gh0, qh0); o.y = silu_mul(gh1, qh1);                  \
            o.z = silu_mul(gh2, qh2); o.w = silu_mul(gh3, qh3);                  \
            *(float4*)(g_act + (size_t)(off + gmL + 1) * I_DIM + n0 + tx * 4) = o; \
        }                                                                        \
    } while (0)

    EPI_GU(0, g00, g01, g02, g03, u00, u01, u02, u03);
    EPI_GU(1, g10, g11, g12, g13, u10, u11, u12, u13);
    EPI_GU(2, g20, g21, g22, g23, u20, u21, u22, u23);
    EPI_GU(3, g30, g31, g32, g33, u30, u31, u32, u33);
#undef EPI_GU
}

// ---------------- phase B: down = act_e @ Wd_e (same pipeline structure) -----------
__global__ __launch_bounds__(128, 3)
void down_kernel(const float* __restrict__ wd) {
    int e = blockIdx.z;
    int cnt = g_cnt[e];
    int m0 = blockIdx.y * BM;
    if (m0 >= cnt) return;
    int n0 = blockIdx.x * BN;
    int off = g_off[e];

    __shared__ __align__(16) float sA[2][BK][BM];
    __shared__ __align__(16) float sB[2][BK][BN];

    int tid = threadIdx.x;
    int tx = tid & 15;
    int ty = tid >> 4;

    unsigned long long d00=0,d01=0,d02=0,d03=0, d10=0,d11=0,d12=0,d13=0;
    unsigned long long d20=0,d21=0,d22=0,d23=0, d30=0,d31=0,d32=0,d33=0;

    const float* wde = wd + (size_t)e * I_DIM * H_DIM;

    int am = tid >> 1;
    int ak = (tid & 1) * 8;
    const float* arow = 0;
    { int mr = m0 + am; if (mr < cnt) arow = g_act + (size_t)(off + mr) * I_DIM; }

    int bk = tid >> 3;
    int bn = (tid & 7) * 8;

    float4 pa0, pa1, pb0, pb1;

#define LOADCH(k0_) do {                                                         \
    if (arow) {                                                                  \
        pa0 = *(const float4*)(arow + (k0_) + ak);                               \
        pa1 = *(const float4*)(arow + (k0_) + ak + 4);                           \
    } else {                                                                     \
        pa0.x = pa0.y = pa0.z = pa0.w = 0.f;                                     \
        pa1 = pa0;                                                               \
    }                                                                            \
    const float* bp_ = wde + (size_t)((k0_) + bk) * H_DIM + n0 + bn;             \
    pb0 = *(const float4*)bp_;  pb1 = *(const float4*)(bp_ + 4);                 \
} while (0)

    LOADCH(0);

    int buf = 0;
    for (int k0 = 0; k0 < I_DIM; k0 += BK, buf ^= 1) {
        sA[buf][ak + 0][am] = pa0.x;
        sA[buf][ak + 1][am] = pa0.y;
        sA[buf][ak + 2][am] = pa0.z;
        sA[buf][ak + 3][am] = pa0.w;
        sA[buf][ak + 4][am] = pa1.x;
        sA[buf][ak + 5][am] = pa1.y;
        sA[buf][ak + 6][am] = pa1.z;
        sA[buf][ak + 7][am] = pa1.w;
        *(float4*)&sB[buf][bk][bn]     = pb0;
        *(float4*)&sB[buf][bk][bn + 4] = pb1;
        __syncthreads();

        if (k0 + BK < I_DIM) LOADCH(k0 + BK);

        #pragma unroll
        for (int kk = 0; kk < BK; kk++) {
            ulonglong2 av0 = *(const ulonglong2*)&sA[buf][kk][ty * 8];
            ulonglong2 av1 = *(const ulonglong2*)&sA[buf][kk][ty * 8 + 4];
            float4 bv = *(const float4*)&sB[buf][kk][tx * 4];
            unsigned long long pb0q, pb1q, pb2q, pb3q;
            PACK2(pb0q, bv.x); PACK2(pb1q, bv.y); PACK2(pb2q, bv.z); PACK2(pb3q, bv.w);

            FMA2(d00, av0.x, pb0q); FMA2(d01, av0.x, pb1q); FMA2(d02, av0.x, pb2q); FMA2(d03, av0.x, pb3q);
            FMA2(d10, av0.y, pb0q); FMA2(d11, av0.y, pb1q); FMA2(d12, av0.y, pb2q); FMA2(d13, av0.y, pb3q);
            FMA2(d20, av1.x, pb0q); FMA2(d21, av1.x, pb1q); FMA2(d22, av1.x, pb2q); FMA2(d23, av1.x, pb3q);
            FMA2(d30, av1.y, pb0q); FMA2(d31, av1.y, pb1q); FMA2(d32, av1.y, pb2q); FMA2(d33, av1.y, pb3q);
        }
    }
#undef LOADCH

#define EPI_DN(P, DA, DB, DC, DD)                                                \
    do {                                                                         \
        float l0, h0, l1, h1, l2, h2, l3, h3;                                    \
        UNPACK2(l0, h0, DA); UNPACK2(l1, h1, DB);                                \
        UNPACK2(l2, h2, DC); UNPACK2(l3, h3, DD);                                \
        int gmL = m0 + ty * 8 + 2 * (P);                                         \
        if (gmL < cnt) {                                                         \
            float4 o; o.x = l0; o.y = l1; o.z = l2; o.w = l3;                    \
            *(float4*)(g_down + (size_t)(off + gmL) * H_DIM + n0 + tx * 4) = o;  \
        }                                                                        \
        if (gmL + 1 < cnt) {                                                     \
            float4 o; o.x = h0; o.y = h1; o.z = h2; o.w = h3;                    \
            *(float4*)(g_down + (size_t)(off + gmL + 1) * H_DIM + n0 + tx * 4) = o; \
        }                                                                        \
    } while (0)

    EPI_DN(0, d00, d01, d02, d03);
    EPI_DN(1, d10, d11, d12, d13);
    EPI_DN(2, d20, d21, d22, d23);
    EPI_DN(3, d30, d31, d32, d33);
#undef EPI_DN
}

// ---------------- combine (proven) ----------------
__global__ void combine_kernel(float* __restrict__ out) {
    int t = blockIdx.x;
    __shared__ int s0s, s1s;
    __shared__ float w0s, w1s;
    if (threadIdx.x == 0) {
        int e0 = g_sel_e[2 * t], e1 = g_sel_e[2 * t + 1];
        s0s = g_off[e0] + g_sel_r[2 * t];
        s1s = g_off[e1] + g_sel_r[2 * t + 1];
        w0s = g_sel_w[2 * t];
        w1s = g_sel_w[2 * t + 1];
    }
    __syncthreads();
    const float* d0 = g_down + (size_t)s0s * H_DIM;
    const float* d1 = g_down + (size_t)s1s * H_DIM;
    float* o = out + (size_t)t * H_DIM;
    float w0 = w0s, w1 = w1s;
    for (int h = threadIdx.x; h < H_DIM; h += blockDim.x)
        o[h] = w0 * d0[h] + w1 * d1[h];
}

// ---------------- launch (identical shape to proven R9) ----------------
extern "C" void kernel_launch(void* const* d_in, const int* in_sizes, int n_in,
                              void* d_out, int out_size) {
    const float* x  = (const float*)d_in[0];
    const float* rw = (const float*)d_in[1];
    const float* wg = (const float*)d_in[2];
    const float* wu = (const float*)d_in[3];
    const float* wd = (const float*)d_in[4];
    float* out = (float*)d_out;

    int extras = (out_size >= T_TOK * H_DIM + T_TOK * NE + T_TOK * TOPK) ? 1 : 0;

    reset_kernel<<<1, 32>>>();
    router_kernel<<<T_TOK, 256>>>(x, rw, out, extras);
    scan_kernel<<<1, 1>>>();

    dim3 ga(I_DIM / BN, T_TOK / BM, NE);   // (64, 64, 8)
    gateup_kernel<<<ga, 128>>>(x, wg, wu);

    dim3 gb(H_DIM / BN, T_TOK / BM, NE);   // (16, 64, 8)
    down_kernel<<<gb, 128>>>(wd);

    combine_kernel<<<T_TOK, 256>>>(out);
}

// round 11
// speedup vs baseline: 1.0622x; 1.0060x over previous
#include <cuda_runtime.h>
#include <math.h>
#include <stdint.h>

#define T_TOK 4096
#define H_DIM 1024
#define I_DIM 4096
#define NE 8
#define TOPK 2
#define ROWS_TOT (T_TOK * TOPK)
#define ROWS_PAD (ROWS_TOT + 128)

#define BM 128
#define BN 64
#define BK 16

// ---------------- scratch (static device globals; ~162 MiB, proven level) ----------
__device__ int   g_cnt[NE];
__device__ int   g_off[NE];
__device__ int   g_tok[NE * T_TOK];
__device__ int   g_sel_e[T_TOK * TOPK];
__device__ int   g_sel_r[T_TOK * TOPK];
__device__ float g_sel_w[T_TOK * TOPK];
__device__ float g_act[(size_t)ROWS_PAD * I_DIM];    // silu(g)*u
__device__ float g_down[(size_t)ROWS_PAD * H_DIM];   // down proj per row

// ---------------- packed f32x2 helpers (guard-proven in R9/R10) --------------------
#define FMA2(d, a, b) \
    asm("fma.rn.f32x2 %0, %1, %2, %0;" : "+l"(d) : "l"(a), "l"(b))
#define PACK2(d, f) \
    asm("mov.b64 %0, {%1, %1};" : "=l"(d) : "f"(f))
#define UNPACK2(lo, hi, d) \
    asm("mov.b64 {%0, %1}, %2;" : "=f"(lo), "=f"(hi) : "l"(d))

__device__ __forceinline__ float silu_mul(float g, float u) {
    return (g / (1.f + expf(-g))) * u;
}

// ---------------- reset / router / scan (proven, unchanged) ----------------
__global__ void reset_kernel() { if (threadIdx.x < NE) g_cnt[threadIdx.x] = 0; }

__global__ void router_kernel(const float* __restrict__ x, const float* __restrict__ rw,
                              float* __restrict__ out, int extras) {
    int t = blockIdx.x, tid = threadIdx.x;
    int e = tid >> 5, lane = tid & 31;
    const float* xt = x + (size_t)t * H_DIM;
    float s = 0.f;
    for (int h = lane; h < H_DIM; h += 32) s += xt[h] * rw[h * NE + e];
    #pragma unroll
    for (int o = 16; o > 0; o >>= 1) s += __shfl_xor_sync(0xffffffffu, s, o);
    __shared__ float lg[NE];
    if (lane == 0) lg[e] = s;
    __syncthreads();
    if (tid == 0) {
        float mx = lg[0];
        #pragma unroll
        for (int i = 1; i < NE; i++) mx = fmaxf(mx, lg[i]);
        float p[NE];
        #pragma unroll
        for (int i = 0; i < NE; i++) p[i] = expf(lg[i] - mx);
        int e0 = 0;
        #pragma unroll
        for (int i = 1; i < NE; i++) if (p[i] > p[e0]) e0 = i;
        int e1 = (e0 == 0) ? 1 : 0;
        #pragma unroll
        for (int i = 0; i < NE; i++) if (i != e0 && p[i] > p[e1]) e1 = i;
        float p0 = p[e0], p1 = p[e1];
        float inv = 1.f / (p0 + p1);
        int r0 = atomicAdd(&g_cnt[e0], 1);
        int r1 = atomicAdd(&g_cnt[e1], 1);
        g_tok[e0 * T_TOK + r0] = t;
        g_tok[e1 * T_TOK + r1] = t;
        g_sel_e[2 * t] = e0;     g_sel_r[2 * t] = r0;     g_sel_w[2 * t] = p0 * inv;
        g_sel_e[2 * t + 1] = e1; g_sel_r[2 * t + 1] = r1; g_sel_w[2 * t + 1] = p1 * inv;
        if (extras) {
            float* lo = out + (size_t)T_TOK * H_DIM;
            #pragma unroll
            for (int i = 0; i < NE; i++) lo[(size_t)t * NE + i] = lg[i];
            float* se = out + (size_t)T_TOK * H_DIM + (size_t)T_TOK * NE;
            se[2 * t] = (float)e0;
            se[2 * t + 1] = (float)e1;
        }
    }
}

__global__ void scan_kernel() {
    int o = 0;
    for (int e = 0; e < NE; e++) { g_off[e] = o; o += g_cnt[e]; }
}

// ==================================================================================
// Gate/up GEMM, FFMA2, thread tile 16m x 4n PER MATRIX (was 8m x 4n).
// Rationale: L1tex was the top pipe (81.5% > fma 69%); widening m doubles FLOPs per
// LDS byte (2.0 -> 2.67) and halves per-FLOP issue overhead. BM=128, BN=64, BK=16,
// 128 threads, R9-proven sync staging, named-scalar u64 accumulators (64 = 128 regs).
// __launch_bounds__(128,2): cap 256 regs, est ~214 -> no spill (alloc-guard rule).
// ==================================================================================

#define DECLP(P) \
    unsigned long long gp##P##0=0, gp##P##1=0, gp##P##2=0, gp##P##3=0, \
                       up##P##0=0, up##P##1=0, up##P##2=0, up##P##3=0

#define FMAP(P, A) do { \
    FMA2(gp##P##0, (A), pg0); FMA2(gp##P##1, (A), pg1); \
    FMA2(gp##P##2, (A), pg2); FMA2(gp##P##3, (A), pg3); \
    FMA2(up##P##0, (A), pu0); FMA2(up##P##1, (A), pu1); \
    FMA2(up##P##2, (A), pu2); FMA2(up##P##3, (A), pu3); \
} while (0)

__global__ __launch_bounds__(128, 2)
void gateup_kernel(const float* __restrict__ x,
                   const float* __restrict__ wg,
                   const float* __restrict__ wu) {
    int e = blockIdx.z;
    int cnt = g_cnt[e];
    int m0 = blockIdx.y * BM;
    if (m0 >= cnt) return;
    int n0 = blockIdx.x * BN;
    int off = g_off[e];

    __shared__ __align__(16) float sA[BK][BM];    // 8 KB
    __shared__ __align__(16) float sBg[BK][BN];   // 4 KB
    __shared__ __align__(16) float sBu[BK][BN];   // 4 KB

    int tid = threadIdx.x;
    int tx = tid & 15;     // 16 n-cols of 4
    int ty = tid >> 4;     // 8 m-slabs of 16

    DECLP(0); DECLP(1); DECLP(2); DECLP(3);
    DECLP(4); DECLP(5); DECLP(6); DECLP(7);

    const float* wge = wg + (size_t)e * H_DIM * I_DIM;
    const float* wue = wu + (size_t)e * H_DIM * I_DIM;

    // A staging: thread tid owns row am=tid, all 16 k of the chunk
    int am = tid;
    const float* xrow = 0;
    { int mr = m0 + am; if (mr < cnt) xrow = x + (size_t)g_tok[e * T_TOK + mr] * H_DIM; }

    // B staging: same geometry as proven R9
    int bk = tid >> 3;        // 0..15
    int bn = (tid & 7) * 8;   // 0..56

    int mb = ty * 16;         // this thread's m base

    for (int k0 = 0; k0 < H_DIM; k0 += BK) {
        float4 a0, a1, a2, a3;
        if (xrow) {
            a0 = *(const float4*)(xrow + k0);
            a1 = *(const float4*)(xrow + k0 + 4);
            a2 = *(const float4*)(xrow + k0 + 8);
            a3 = *(const float4*)(xrow + k0 + 12);
        } else {
            a0.x = a0.y = a0.z = a0.w = 0.f;
            a1 = a0; a2 = a0; a3 = a0;
        }
        const float* bgp = wge + (size_t)(k0 + bk) * I_DIM + n0 + bn;
        const float* bup = wue + (size_t)(k0 + bk) * I_DIM + n0 + bn;
        float4 bg0 = *(const float4*)bgp;
        float4 bg1 = *(const float4*)(bgp + 4);
        float4 bu0 = *(const float4*)bup;
        float4 bu1 = *(const float4*)(bup + 4);

        __syncthreads();
        sA[0][am]  = a0.x;  sA[1][am]  = a0.y;  sA[2][am]  = a0.z;  sA[3][am]  = a0.w;
        sA[4][am]  = a1.x;  sA[5][am]  = a1.y;  sA[6][am]  = a1.z;  sA[7][am]  = a1.w;
        sA[8][am]  = a2.x;  sA[9][am]  = a2.y;  sA[10][am] = a2.z;  sA[11][am] = a2.w;
        sA[12][am] = a3.x;  sA[13][am] = a3.y;  sA[14][am] = a3.z;  sA[15][am] = a3.w;
        *(float4*)&sBg[bk][bn]     = bg0;
        *(float4*)&sBg[bk][bn + 4] = bg1;
        *(float4*)&sBu[bk][bn]     = bu0;
        *(float4*)&sBu[bk][bn + 4] = bu1;
        __syncthreads();

        #pragma unroll
        for (int kk = 0; kk < BK; kk++) {
            ulonglong2 av0 = *(const ulonglong2*)&sA[kk][mb];       // pairs m0m1, m2m3
            ulonglong2 av1 = *(const ulonglong2*)&sA[kk][mb + 4];   // m4m5, m6m7
            ulonglong2 av2 = *(const ulonglong2*)&sA[kk][mb + 8];   // m8m9, m10m11
            ulonglong2 av3 = *(const ulonglong2*)&sA[kk][mb + 12];  // m12m13, m14m15
            float4 bgv = *(const float4*)&sBg[kk][tx * 4];
            float4 buv = *(const float4*)&sBu[kk][tx * 4];
            unsigned long long pg0, pg1, pg2, pg3, pu0, pu1, pu2, pu3;
            PACK2(pg0, bgv.x); PACK2(pg1, bgv.y); PACK2(pg2, bgv.z); PACK2(pg3, bgv.w);
            PACK2(pu0, buv.x); PACK2(pu1, buv.y); PACK2(pu2, buv.z); PACK2(pu3, buv.w);

            FMAP(0, av0.x); FMAP(1, av0.y);
            FMAP(2, av1.x); FMAP(3, av1.y);
            FMAP(4, av2.x); FMAP(5, av2.y);
            FMAP(6, av3.x); FMAP(7, av3.y);
        }
    }

    // ---- epilogue: silu(g)*u per m-pair ----
#define EPIP(P)                                                                  \
    do {                                                                         \
        float gl0, gh0, gl1, gh1, gl2, gh2, gl3, gh3;                            \
        float ql0, qh0, ql1, qh1, ql2, qh2, ql3, qh3;                            \
        UNPACK2(gl0, gh0, gp##P##0); UNPACK2(gl1, gh1, gp##P##1);                \
        UNPACK2(gl2, gh2, gp##P##2); UNPACK2(gl3, gh3, gp##P##3);                \
        UNPACK2(ql0, qh0, up##P##0); UNPACK2(ql1, qh1, up##P##1);                \
        UNPACK2(ql2, qh2, up##P##2); UNPACK2(ql3, qh3, up##P##3);                \
        int gmL = m0 + mb + 2 * (P);                                             \
        if (gmL < cnt) {                                                         \
            float4 o;                                                            \
            o.x = silu_mul(gl0, ql0); o.y = silu_mul(gl1, ql1);                  \
            o.z = silu_mul(gl2, ql2); o.w = silu_mul(gl3, ql3);                  \
            *(float4*)(g_act + (size_t)(off + gmL) * I_DIM + n0 + tx * 4) = o;   \
        }                                                                        \
        if (gmL + 1 < cnt) {                                                     \
            float4 o;                                                            \
            o.x = silu_mul(gh0, qh0); o.y = silu_mul(gh1, qh1);                  \
            o.z = silu_mul(gh2, qh2); o.w = silu_mul(gh3, qh3);                  \
            *(float4*)(g_act + (size_t)(off + gmL + 1) * I_DIM + n0 + tx * 4) = o; \
        }                                                                        \
    } while (0)

    EPIP(0); EPIP(1); EPIP(2); EPIP(3);
    EPIP(4); EPIP(5); EPIP(6); EPIP(7);
#undef EPIP
}

// ==================================================================================
// Down GEMM: same 16m x 4n widening (3.2 FLOP/LDS-byte), single matrix.
// acc = 32 u64 (64 regs); __launch_bounds__(128,3) cap 168, est ~142 -> no spill.
// ==================================================================================

#define DDECL(P) \
    unsigned long long dp##P##0=0, dp##P##1=0, dp##P##2=0, dp##P##3=0

#define DFMAP(P, A) do { \
    FMA2(dp##P##0, (A), pb0); FMA2(dp##P##1, (A), pb1); \
    FMA2(dp##P##2, (A), pb2); FMA2(dp##P##3, (A), pb3); \
} while (0)

__global__ __launch_bounds__(128, 3)
void down_kernel(const float* __restrict__ wd) {
    int e = blockIdx.z;
    int cnt = g_cnt[e];
    int m0 = blockIdx.y * BM;
    if (m0 >= cnt) return;
    int n0 = blockIdx.x * BN;
    int off = g_off[e];

    __shared__ __align__(16) float sA[BK][BM];   // 8 KB
    __shared__ __align__(16) float sB[BK][BN];   // 4 KB

    int tid = threadIdx.x;
    int tx = tid & 15;
    int ty = tid >> 4;

    DDECL(0); DDECL(1); DDECL(2); DDECL(3);
    DDECL(4); DDECL(5); DDECL(6); DDECL(7);

    const float* wde = wd + (size_t)e * I_DIM * H_DIM;

    int am = tid;
    const float* arow = 0;
    { int mr = m0 + am; if (mr < cnt) arow = g_act + (size_t)(off + mr) * I_DIM; }

    int bk = tid >> 3;
    int bn = (tid & 7) * 8;
    int mb = ty * 16;

    for (int k0 = 0; k0 < I_DIM; k0 += BK) {
        float4 a0, a1, a2, a3;
        if (arow) {
            a0 = *(const float4*)(arow + k0);
            a1 = *(const float4*)(arow + k0 + 4);
            a2 = *(const float4*)(arow + k0 + 8);
            a3 = *(const float4*)(arow + k0 + 12);
        } else {
            a0.x = a0.y = a0.z = a0.w = 0.f;
            a1 = a0; a2 = a0; a3 = a0;
        }
        const float* bp = wde + (size_t)(k0 + bk) * H_DIM + n0 + bn;
        float4 b0 = *(const float4*)bp;
        float4 b1 = *(const float4*)(bp + 4);

        __syncthreads();
        sA[0][am]  = a0.x;  sA[1][am]  = a0.y;  sA[2][am]  = a0.z;  sA[3][am]  = a0.w;
        sA[4][am]  = a1.x;  sA[5][am]  = a1.y;  sA[6][am]  = a1.z;  sA[7][am]  = a1.w;
        sA[8][am]  = a2.x;  sA[9][am]  = a2.y;  sA[10][am] = a2.z;  sA[11][am] = a2.w;
        sA[12][am] = a3.x;  sA[13][am] = a3.y;  sA[14][am] = a3.z;  sA[15][am] = a3.w;
        *(float4*)&sB[bk][bn]     = b0;
        *(float4*)&sB[bk][bn + 4] = b1;
        __syncthreads();

        #pragma unroll
        for (int kk = 0; kk < BK; kk++) {
            ulonglong2 av0 = *(const ulonglong2*)&sA[kk][mb];
            ulonglong2 av1 = *(const ulonglong2*)&sA[kk][mb + 4];
            ulonglong2 av2 = *(const ulonglong2*)&sA[kk][mb + 8];
            ulonglong2 av3 = *(const ulonglong2*)&sA[kk][mb + 12];
            float4 bv = *(const float4*)&sB[kk][tx * 4];
            unsigned long long pb0, pb1, pb2, pb3;
            PACK2(pb0, bv.x); PACK2(pb1, bv.y); PACK2(pb2, bv.z); PACK2(pb3, bv.w);

            DFMAP(0, av0.x); DFMAP(1, av0.y);
            DFMAP(2, av1.x); DFMAP(3, av1.y);
            DFMAP(4, av2.x); DFMAP(5, av2.y);
            DFMAP(6, av3.x); DFMAP(7, av3.y);
        }
    }

#define EPID(P)                                                                  \
    do {                                                                         \
        float l0, h0, l1, h1, l2, h2, l3, h3;                                    \
        UNPACK2(l0, h0, dp##P##0); UNPACK2(l1, h1, dp##P##1);                    \
        UNPACK2(l2, h2, dp##P##2); UNPACK2(l3, h3, dp##P##3);                    \
        int gmL = m0 + mb + 2 * (P);                                             \
        if (gmL < cnt) {                                                         \
            float4 o; o.x = l0; o.y = l1; o.z = l2; o.w = l3;                    \
            *(float4*)(g_down + (size_t)(off + gmL) * H_DIM + n0 + tx * 4) = o;  \
        }                                                                        \
        if (gmL + 1 < cnt) {                                                     \
            float4 o; o.x = h0; o.y = h1; o.z = h2; o.w = h3;                    \
            *(float4*)(g_down + (size_t)(off + gmL + 1) * H_DIM + n0 + tx * 4) = o; \
        }                                                                        \
    } while (0)

    EPID(0); EPID(1); EPID(2); EPID(3);
    EPID(4); EPID(5); EPID(6); EPID(7);
#undef EPID
}

// ---------------- combine (proven) ----------------
__global__ void combine_kernel(float* __restrict__ out) {
    int t = blockIdx.x;
    __shared__ int s0s, s1s;
    __shared__ float w0s, w1s;
    if (threadIdx.x == 0) {
        int e0 = g_sel_e[2 * t], e1 = g_sel_e[2 * t + 1];
        s0s = g_off[e0] + g_sel_r[2 * t];
        s1s = g_off[e1] + g_sel_r[2 * t + 1];
        w0s = g_sel_w[2 * t];
        w1s = g_sel_w[2 * t + 1];
    }
    __syncthreads();
    const float* d0 = g_down + (size_t)s0s * H_DIM;
    const float* d1 = g_down + (size_t)s1s * H_DIM;
    float* o = out + (size_t)t * H_DIM;
    float w0 = w0s, w1 = w1s;
    for (int h = threadIdx.x; h < H_DIM; h += blockDim.x)
        o[h] = w0 * d0[h] + w1 * d1[h];
}

// ---------------- launch ----------------
extern "C" void kernel_launch(void* const* d_in, const int* in_sizes, int n_in,
                              void* d_out, int out_size) {
    const float* x  = (const float*)d_in[0];
    const float* rw = (const float*)d_in[1];
    const float* wg = (const float*)d_in[2];
    const float* wu = (const float*)d_in[3];
    const float* wd = (const float*)d_in[4];
    float* out = (float*)d_out;

    int extras = (out_size >= T_TOK * H_DIM + T_TOK * NE + T_TOK * TOPK) ? 1 : 0;

    reset_kernel<<<1, 32>>>();
    router_kernel<<<T_TOK, 256>>>(x, rw, out, extras);
    scan_kernel<<<1, 1>>>();

    dim3 ga(I_DIM / BN, T_TOK / BM, NE);   // (64, 32, 8)
    gateup_kernel<<<ga, 128>>>(x, wg, wu);

    dim3 gb(H_DIM / BN, T_TOK / BM, NE);   // (16, 32, 8)
    down_kernel<<<gb, 128>>>(wd);

    combine_kernel<<<T_TOK, 256>>>(out);
}